// round 12
// baseline (speedup 1.0000x reference)
#include <cuda_runtime.h>
#include <cuda_bf16.h>
#include <cstdint>

// DynamicSparseAttention: B=4,H=16,S=2048,D=64
// d_out layout (f32): [out: BH*S*D][attn: BH*S*S][tau: BH*S]
#define S_LEN 2048
#define D_DIM 64
#define BH    64
#define NELEM (BH * S_LEN * D_DIM)                 // 8388608
#define SELEM ((size_t)BH * S_LEN * S_LEN)         // 268435456

// pre-split bf16 hi/lo scratch (device globals: allocation-free scratch)
__device__ __align__(16) __nv_bfloat16 g_qhi[NELEM];
__device__ __align__(16) __nv_bfloat16 g_qlo[NELEM];
__device__ __align__(16) __nv_bfloat16 g_khi[NELEM];
__device__ __align__(16) __nv_bfloat16 g_klo[NELEM];
__device__ __align__(16) __nv_bfloat16 g_vhi[NELEM];
__device__ __align__(16) __nv_bfloat16 g_vlo[NELEM];
// scores / normalized-attn hi/lo scratch (reused in place)
__device__ __align__(16) __nv_bfloat16 g_shi[SELEM];
__device__ __align__(16) __nv_bfloat16 g_slo[SELEM];

// ---------------------------------------------------------------- helpers
__device__ __forceinline__ uint32_t smem_u32(const void* p) {
    uint32_t a;
    asm("{ .reg .u64 t; cvta.to.shared.u64 t, %1; cvt.u32.u64 %0, t; }"
        : "=r"(a) : "l"(p));
    return a;
}

// 128B-row tile, 16B-chunk XOR swizzle
__device__ __forceinline__ uint32_t toff(int r, int ch) {
    return (uint32_t)(r * 128 + ((ch ^ (r & 7)) << 4));
}

__device__ __forceinline__ void ldmx4(uint32_t* r, uint32_t a) {
    asm volatile("ldmatrix.sync.aligned.m8n8.x4.shared.b16 {%0,%1,%2,%3}, [%4];"
        : "=r"(r[0]), "=r"(r[1]), "=r"(r[2]), "=r"(r[3]) : "r"(a));
}
__device__ __forceinline__ void ldmx4t(uint32_t* r, uint32_t a) {
    asm volatile("ldmatrix.sync.aligned.m8n8.x4.trans.shared.b16 {%0,%1,%2,%3}, [%4];"
        : "=r"(r[0]), "=r"(r[1]), "=r"(r[2]), "=r"(r[3]) : "r"(a));
}
__device__ __forceinline__ void mma_bf16(float* c, const uint32_t* a, const uint32_t* b) {
    asm volatile(
        "mma.sync.aligned.m16n8k16.row.col.f32.bf16.bf16.f32 "
        "{%0,%1,%2,%3}, {%4,%5,%6,%7}, {%8,%9}, {%0,%1,%2,%3};"
        : "+f"(c[0]), "+f"(c[1]), "+f"(c[2]), "+f"(c[3])
        : "r"(a[0]), "r"(a[1]), "r"(a[2]), "r"(a[3]), "r"(b[0]), "r"(b[1]));
}

__device__ __forceinline__ void cpa16(uint32_t dst, const void* src) {
    asm volatile("cp.async.cg.shared.global [%0], [%1], 16;"
                 :: "r"(dst), "l"(__cvta_generic_to_global(src)));
}
__device__ __forceinline__ void cpa_commit() {
    asm volatile("cp.async.commit_group;");
}
template <int N>
__device__ __forceinline__ void cpa_wait() {
    asm volatile("cp.async.wait_group %0;" :: "n"(N));
}

__device__ __forceinline__ uint32_t bfpair(float a, float b) {
    __nv_bfloat162 t;
    t.x = __float2bfloat16(a);
    t.y = __float2bfloat16(b);
    return *reinterpret_cast<uint32_t*>(&t);
}
__device__ __forceinline__ float2 bf2f2(uint32_t u) {
    __nv_bfloat162 t = *reinterpret_cast<__nv_bfloat162*>(&u);
    return make_float2(__bfloat162float(t.x), __bfloat162float(t.y));
}
// split pair of floats into hi uint32 + lo(residual) uint32
__device__ __forceinline__ void split2(float a, float b, uint32_t& h, uint32_t& l) {
    __nv_bfloat16 ha = __float2bfloat16(a), hb = __float2bfloat16(b);
    __nv_bfloat162 hp; hp.x = ha; hp.y = hb;
    h = *reinterpret_cast<uint32_t*>(&hp);
    l = bfpair(a - __bfloat162float(ha), b - __bfloat162float(hb));
}
// split float4 -> uint2 hi + uint2 lo
__device__ __forceinline__ void split4(float4 f, uint2& hi, uint2& lo) {
    split2(f.x, f.y, hi.x, lo.x);
    split2(f.z, f.w, hi.y, lo.y);
}

// -------------------------------------------------------------------------
// Kernel 0: pre-split Q*0.125, K, V into bf16 hi/lo scratch.
// -------------------------------------------------------------------------
__global__ __launch_bounds__(256) void dsa_prep(
    const float* __restrict__ q, const float* __restrict__ k,
    const float* __restrict__ v)
{
    const int stride = gridDim.x * 256;
    const float4* q4 = (const float4*)q;
    const float4* k4 = (const float4*)k;
    const float4* v4 = (const float4*)v;
    uint2* qh = (uint2*)g_qhi; uint2* ql = (uint2*)g_qlo;
    uint2* kh = (uint2*)g_khi; uint2* kl = (uint2*)g_klo;
    uint2* vh = (uint2*)g_vhi; uint2* vl = (uint2*)g_vlo;

    for (int i = blockIdx.x * 256 + threadIdx.x; i < NELEM / 4; i += stride) {
        float4 fq = q4[i];
        fq.x *= 0.125f; fq.y *= 0.125f; fq.z *= 0.125f; fq.w *= 0.125f;
        uint2 hi, lo;
        split4(fq, hi, lo); qh[i] = hi; ql[i] = lo;
        split4(k4[i], hi, lo); kh[i] = hi; kl[i] = lo;
        split4(v4[i], hi, lo); vh[i] = hi; vl[i] = lo;
    }
}

// -------------------------------------------------------------------------
// Kernel 1: raw scores = (Q*scale) K^T -> bf16 hi/lo scratch (g_shi/g_slo).
// CTA = 128-row q-stripe over 16 k-tiles. 512 threads, 16 warps (4m x 4n).
// A frags in registers; K tiles via cp.async double-buffered. SMEM 96KB.
// -------------------------------------------------------------------------
#define SC_SMEM 98304
__global__ __launch_bounds__(512) void dsa_scores_kernel()
{
    extern __shared__ __align__(16) char sm[];
    const uint32_t sb = smem_u32(sm);
    const uint32_t QHI = 0, QLO = 16384;      // K bufs at 32768 + b*32768

    const int tid = threadIdx.x, lane = tid & 31, wid = tid >> 5;
    const int qt = blockIdx.x, bh = blockIdx.y;

    const __nv_bfloat16* Qh = g_qhi + ((size_t)bh * S_LEN + (size_t)qt * 128) * D_DIM;
    const __nv_bfloat16* Ql = g_qlo + ((size_t)bh * S_LEN + (size_t)qt * 128) * D_DIM;
    const __nv_bfloat16* Kh = g_khi + (size_t)bh * S_LEN * D_DIM;
    const __nv_bfloat16* Kl = g_klo + (size_t)bh * S_LEN * D_DIM;

    // group 0: Q hi/lo + K tile 0
    #pragma unroll
    for (int i = 0; i < 2; i++) {
        int idx = tid + i * 512;
        int r = idx >> 3, ch = idx & 7;
        uint32_t o = toff(r, ch);
        cpa16(sb + QHI + o, Qh + r * 64 + ch * 8);
        cpa16(sb + QLO + o, Ql + r * 64 + ch * 8);
        cpa16(sb + 32768 + o, Kh + r * 64 + ch * 8);
        cpa16(sb + 32768 + 16384 + o, Kl + r * 64 + ch * 8);
    }
    cpa_commit();
    // group 1: K tile 1
    #pragma unroll
    for (int i = 0; i < 2; i++) {
        int idx = tid + i * 512;
        int r = idx >> 3, ch = idx & 7;
        uint32_t o = toff(r, ch);
        cpa16(sb + 65536 + o, Kh + (size_t)(128 + r) * 64 + ch * 8);
        cpa16(sb + 65536 + 16384 + o, Kl + (size_t)(128 + r) * 64 + ch * 8);
    }
    cpa_commit();
    cpa_wait<1>();
    __syncthreads();

    const int wm = wid >> 2, wn = wid & 3;
    const int alr = lane & 7, alm = (lane >> 3) & 1, alk = lane >> 4;
    const int brow_off = ((lane >> 4) << 3) + (lane & 7);
    const int bchk_off = (lane >> 3) & 1;

    // A fragments cached in registers for the whole kernel
    uint32_t ah[4][2][4], al[4][2][4];
    #pragma unroll
    for (int ks = 0; ks < 4; ks++)
        #pragma unroll
        for (int mi = 0; mi < 2; mi++) {
            int row = wm * 32 + mi * 16 + alr + alm * 8;
            uint32_t o = toff(row, ks * 2 + alk);
            ldmx4(ah[ks][mi], sb + QHI + o);
            ldmx4(al[ks][mi], sb + QLO + o);
        }

    const int qr = lane >> 2, qc = (lane & 3) * 2;
    const size_t rowbase = (size_t)bh * S_LEN + (size_t)qt * 128;
    uint32_t* SH = (uint32_t*)g_shi;
    uint32_t* SL = (uint32_t*)g_slo;

    for (int t = 0; t < 16; t++) {
        const uint32_t KB = sb + 32768 + (uint32_t)(t & 1) * 32768;

        float acc[2][4][4] = {};
        #pragma unroll
        for (int ks = 0; ks < 4; ks++) {
            uint32_t bh_[2][4], bl_[2][4];
            #pragma unroll
            for (int nj = 0; nj < 2; nj++) {
                int row = wn * 32 + nj * 16 + brow_off;
                uint32_t o = toff(row, ks * 2 + bchk_off);
                ldmx4(bh_[nj], KB + o);
                ldmx4(bl_[nj], KB + 16384 + o);
            }
            #pragma unroll
            for (int mi = 0; mi < 2; mi++)
                #pragma unroll
                for (int nj = 0; nj < 2; nj++) {
                    mma_bf16(acc[mi][2*nj],   ah[ks][mi], bh_[nj]);
                    mma_bf16(acc[mi][2*nj+1], ah[ks][mi], bh_[nj] + 2);
                }
            #pragma unroll
            for (int mi = 0; mi < 2; mi++)
                #pragma unroll
                for (int nj = 0; nj < 2; nj++) {
                    mma_bf16(acc[mi][2*nj],   ah[ks][mi], bl_[nj]);
                    mma_bf16(acc[mi][2*nj+1], ah[ks][mi], bl_[nj] + 2);
                }
            #pragma unroll
            for (int mi = 0; mi < 2; mi++)
                #pragma unroll
                for (int nj = 0; nj < 2; nj++) {
                    mma_bf16(acc[mi][2*nj],   al[ks][mi], bh_[nj]);
                    mma_bf16(acc[mi][2*nj+1], al[ks][mi], bh_[nj] + 2);
                }
        }

        // store this k-tile's scores as bf16 hi/lo pairs
        #pragma unroll
        for (int mi = 0; mi < 2; mi++) {
            #pragma unroll
            for (int ni = 0; ni < 4; ni++) {
                int row = wm * 32 + mi * 16 + qr;
                int col = t * 128 + wn * 32 + ni * 8 + qc;
                uint32_t h0, l0, h1, l1;
                split2(acc[mi][ni][0], acc[mi][ni][1], h0, l0);
                split2(acc[mi][ni][2], acc[mi][ni][3], h1, l1);
                size_t i0 = ((rowbase + row) * S_LEN + col) >> 1;
                size_t i1 = ((rowbase + row + 8) * S_LEN + col) >> 1;
                SH[i0] = h0; SL[i0] = l0;
                SH[i1] = h1; SL[i1] = l1;
            }
        }
        __syncthreads();

        if (t + 2 < 16) {
            const __nv_bfloat16* th = Kh + (size_t)(t + 2) * 128 * 64;
            const __nv_bfloat16* tl = Kl + (size_t)(t + 2) * 128 * 64;
            uint32_t dst = sb + 32768 + (uint32_t)(t & 1) * 32768;
            #pragma unroll
            for (int i = 0; i < 2; i++) {
                int idx = tid + i * 512;
                int r = idx >> 3, ch = idx & 7;
                uint32_t o = toff(r, ch);
                cpa16(dst + o, th + r * 64 + ch * 8);
                cpa16(dst + 16384 + o, tl + r * 64 + ch * 8);
            }
            cpa_commit();
            cpa_wait<1>();
        } else {
            cpa_wait<0>();
        }
        __syncthreads();
    }
}

// -------------------------------------------------------------------------
// Kernel 2: read raw scores hi/lo -> variance (ddof=1) -> tau -> softmax.
// Writes f32 attn (output) AND overwrites g_shi/g_slo with normalized bf16.
// Warp-per-row, row in registers. No smem, no barriers.
// -------------------------------------------------------------------------
__global__ __launch_bounds__(256, 2) void dsa_softvar_kernel(
    float* __restrict__ attn, float* __restrict__ tau_out)
{
    const int lane = threadIdx.x & 31;
    const int w = threadIdx.x >> 5;
    const size_t row = (size_t)blockIdx.x * 8 + w;
    uint2* sh = (uint2*)g_shi + row * (S_LEN / 4);
    uint2* sl = (uint2*)g_slo + row * (S_LEN / 4);
    float4* r4 = (float4*)(attn + row * S_LEN);

    float4 d[16];
    float sum = 0.f, sq = 0.f, mx = -3.402823466e38f;
    #pragma unroll
    for (int i = 0; i < 16; i++) {
        uint2 h = sh[lane + 32 * i];
        uint2 l = sl[lane + 32 * i];
        float2 a = bf2f2(h.x), b = bf2f2(h.y);
        float2 c = bf2f2(l.x), e = bf2f2(l.y);
        float4 f = make_float4(a.x + c.x, a.y + c.y, b.x + e.x, b.y + e.y);
        d[i] = f;
        sum += f.x + f.y + f.z + f.w;
        sq = fmaf(f.x, f.x, sq); sq = fmaf(f.y, f.y, sq);
        sq = fmaf(f.z, f.z, sq); sq = fmaf(f.w, f.w, sq);
        mx = fmaxf(mx, fmaxf(fmaxf(f.x, f.y), fmaxf(f.z, f.w)));
    }
    #pragma unroll
    for (int o = 16; o; o >>= 1) {
        sum += __shfl_xor_sync(0xffffffffu, sum, o);
        sq  += __shfl_xor_sync(0xffffffffu, sq, o);
        mx   = fmaxf(mx, __shfl_xor_sync(0xffffffffu, mx, o));
    }

    float mean = sum * (1.0f / S_LEN);
    float var  = (sq - sum * mean) * (1.0f / (S_LEN - 1));  // ddof=1
    float tau  = fmaxf(1.0f / (1.0f + var), 0.3f);          // BASE=1, MIN=0.3
    float itau = 1.0f / tau;
    if (lane == 0) tau_out[row] = tau;

    float ls = 0.f;
    #pragma unroll
    for (int i = 0; i < 16; i++) {
        float4 f = d[i];
        f.x = __expf((f.x - mx) * itau);
        f.y = __expf((f.y - mx) * itau);
        f.z = __expf((f.z - mx) * itau);
        f.w = __expf((f.w - mx) * itau);
        d[i] = f;
        ls += f.x + f.y + f.z + f.w;
    }
    #pragma unroll
    for (int o = 16; o; o >>= 1) ls += __shfl_xor_sync(0xffffffffu, ls, o);
    const float rd = 1.0f / ls;

    #pragma unroll
    for (int i = 0; i < 16; i++) {
        float4 f = d[i];
        f.x *= rd; f.y *= rd; f.z *= rd; f.w *= rd;
        r4[lane + 32 * i] = f;              // f32 attn output
        uint2 hi, lo;
        split4(f, hi, lo);                  // normalized bf16 hi/lo for AV
        sh[lane + 32 * i] = hi;
        sl[lane + 32 * i] = lo;
    }
}

// -------------------------------------------------------------------------
// Kernel 3: out = attn @ V, mma.sync bf16 hi/lo 3-term split.
// Both operands pre-split: pure cp.async + ldmatrix + mma (no pack).
// CTA: 128q x 64d, K=2048 in 32 chunks of 64, double-buffered 96KB SMEM.
// -------------------------------------------------------------------------
#define AV_SMEM 98304
#define AV_BUF  49152

__global__ __launch_bounds__(256) void dsa_av_kernel(float* __restrict__ out)
{
    extern __shared__ __align__(16) char sm[];
    const uint32_t sb = smem_u32(sm);

    const int tid = threadIdx.x, lane = tid & 31, wid = tid >> 5;
    const int bh = blockIdx.y, qt = blockIdx.x;

    const __nv_bfloat16* Ah = g_shi + ((size_t)bh * S_LEN + (size_t)qt * 128) * S_LEN;
    const __nv_bfloat16* Al = g_slo + ((size_t)bh * S_LEN + (size_t)qt * 128) * S_LEN;
    const __nv_bfloat16* Vh = g_vhi + (size_t)bh * S_LEN * D_DIM;
    const __nv_bfloat16* Vl = g_vlo + (size_t)bh * S_LEN * D_DIM;

    const int wm = wid >> 1, wn = wid & 1;
    const int alr = lane & 7, alm = (lane >> 3) & 1, alk = lane >> 4;
    const int vkr_off = ((lane >> 3) & 1) * 8 + (lane & 7);
    const int vnc_off = lane >> 4;

    auto load_chunk = [&](int t, int buf) {
        uint32_t bp = sb + (uint32_t)buf * AV_BUF;
        const size_t kk = (size_t)t * 64;
        #pragma unroll
        for (int i = 0; i < 4; i++) {            // A: 128 x 64 bf16 hi/lo
            int idx = tid + i * 256;
            int r = idx >> 3, ch = idx & 7;
            uint32_t o = toff(r, ch);
            cpa16(bp + o,         Ah + (size_t)r * S_LEN + kk + ch * 8);
            cpa16(bp + 16384 + o, Al + (size_t)r * S_LEN + kk + ch * 8);
        }
        #pragma unroll
        for (int i = 0; i < 2; i++) {            // V: 64 x 64 bf16 hi/lo
            int idx = tid + i * 256;
            int r = idx >> 3, ch = idx & 7;
            uint32_t o = toff(r, ch);
            cpa16(bp + 32768 + o, Vh + (kk + r) * 64 + ch * 8);
            cpa16(bp + 40960 + o, Vl + (kk + r) * 64 + ch * 8);
        }
    };

    load_chunk(0, 0); cpa_commit();
    load_chunk(1, 1); cpa_commit();
    cpa_wait<1>();
    __syncthreads();

    float acc[2][4][4] = {};

    for (int t = 0; t < 32; t++) {
        const uint32_t bp = sb + (uint32_t)(t & 1) * AV_BUF;
        const uint32_t AHI = bp, ALO = bp + 16384, VHI = bp + 32768, VLO = bp + 40960;

        #pragma unroll
        for (int ks = 0; ks < 4; ks++) {
            uint32_t ah[2][4], al[2][4];
            #pragma unroll
            for (int mi = 0; mi < 2; mi++) {
                int row = wm * 32 + mi * 16 + alr + alm * 8;
                uint32_t o = toff(row, ks * 2 + alk);
                ldmx4(ah[mi], AHI + o);
                ldmx4(al[mi], ALO + o);
            }
            uint32_t vh_[2][4], vl_[2][4];
            #pragma unroll
            for (int nj = 0; nj < 2; nj++) {
                int krow = ks * 16 + vkr_off;
                int nc = wn * 4 + nj * 2 + vnc_off;
                uint32_t o = toff(krow, nc);
                ldmx4t(vh_[nj], VHI + o);
                ldmx4t(vl_[nj], VLO + o);
            }
            #pragma unroll
            for (int mi = 0; mi < 2; mi++)
                #pragma unroll
                for (int nj = 0; nj < 2; nj++) {
                    mma_bf16(acc[mi][2*nj],   ah[mi], vh_[nj]);
                    mma_bf16(acc[mi][2*nj+1], ah[mi], vh_[nj] + 2);
                }
            #pragma unroll
            for (int mi = 0; mi < 2; mi++)
                #pragma unroll
                for (int nj = 0; nj < 2; nj++) {
                    mma_bf16(acc[mi][2*nj],   ah[mi], vl_[nj]);
                    mma_bf16(acc[mi][2*nj+1], ah[mi], vl_[nj] + 2);
                }
            #pragma unroll
            for (int mi = 0; mi < 2; mi++)
                #pragma unroll
                for (int nj = 0; nj < 2; nj++) {
                    mma_bf16(acc[mi][2*nj],   al[mi], vh_[nj]);
                    mma_bf16(acc[mi][2*nj+1], al[mi], vh_[nj] + 2);
                }
        }
        __syncthreads();

        if (t + 2 < 32) {
            load_chunk(t + 2, t & 1);
            cpa_commit();
        }
        if (t + 1 < 32) {
            if (t + 2 < 32) cpa_wait<1>(); else cpa_wait<0>();
            __syncthreads();
        }
    }

    const int qr = lane >> 2, qc = (lane & 3) * 2;
    float* Ob = out + ((size_t)bh * S_LEN + (size_t)qt * 128) * D_DIM;
    #pragma unroll
    for (int mi = 0; mi < 2; mi++) {
        #pragma unroll
        for (int ni = 0; ni < 4; ni++) {
            int row = wm * 32 + mi * 16 + qr;
            int col = wn * 32 + ni * 8 + qc;
            float2 v0 = make_float2(acc[mi][ni][0], acc[mi][ni][1]);
            float2 v1 = make_float2(acc[mi][ni][2], acc[mi][ni][3]);
            *(float2*)(Ob + (size_t)row * D_DIM + col) = v0;
            *(float2*)(Ob + (size_t)(row + 8) * D_DIM + col) = v1;
        }
    }
}

// -------------------------------------------------------------------------
extern "C" void kernel_launch(void* const* d_in, const int* in_sizes, int n_in,
                              void* d_out, int out_size)
{
    const float* q = (const float*)d_in[0];
    const float* k = (const float*)d_in[1];
    const float* v = (const float*)d_in[2];

    float* outp = (float*)d_out;                                   // BH*S*D
    float* attn = outp + (size_t)BH * S_LEN * D_DIM;               // BH*S*S
    float* tau  = attn + SELEM;                                    // BH*S

    cudaFuncSetAttribute(dsa_scores_kernel,
                         cudaFuncAttributeMaxDynamicSharedMemorySize, SC_SMEM);
    cudaFuncSetAttribute(dsa_av_kernel,
                         cudaFuncAttributeMaxDynamicSharedMemorySize, AV_SMEM);

    dsa_prep<<<2048, 256>>>(q, k, v);
    dsa_scores_kernel<<<dim3(S_LEN / 128, BH), 512, SC_SMEM>>>();
    dsa_softvar_kernel<<<BH * S_LEN / 8, 256>>>(attn, tau);
    dsa_av_kernel<<<dim3(S_LEN / 128, BH), 256, AV_SMEM>>>(outp);
}